// round 5
// baseline (speedup 1.0000x reference)
#include <cuda_runtime.h>
#include <cuda_bf16.h>
#include <cstdint>

// Problem constants
#define BSZ   32
#define SSZ   1024
#define DSZ   768
#define HSZ   128
#define RSZ   48
#define APP   (SSZ + 1)        // 1025
#define NTOK  (BSZ * SSZ)      // 32768
#define MHEAD (BSZ * APP)      // 32800

// Scratch (device globals)
__device__ __nv_bfloat16 g_headH[(size_t)MHEAD * HSZ];
__device__ __nv_bfloat16 g_headL[(size_t)MHEAD * HSZ];
__device__ float         g_tail [(size_t)NTOK * HSZ];
__device__ __nv_bfloat16 g_KH[(size_t)RSZ * HSZ * HSZ];   // B_r[n][h] hi
__device__ __nv_bfloat16 g_KL[(size_t)RSZ * HSZ * HSZ];   // B_r[n][h] lo
__device__ __nv_bfloat16 g_WH[(size_t)2 * HSZ * DSZ];     // W^T [branch][n][k] hi
__device__ __nv_bfloat16 g_WL[(size_t)2 * HSZ * DSZ];     // W^T [branch][n][k] lo

// ---------------------------------------------------------------------------
// PTX helpers (target-suffix-free)
// ---------------------------------------------------------------------------
__device__ __forceinline__ uint32_t smem_u32(const void* p) {
    uint32_t a;
    asm("{ .reg .u64 t; cvta.to.shared.u64 t, %1; cvt.u32.u64 %0, t; }" : "=r"(a) : "l"(p));
    return a;
}

#define CP16(dst, src) \
    asm volatile("cp.async.cg.shared.global [%0], [%1], 16;" :: "r"(dst), "l"(src) : "memory")
#define CP_COMMIT() asm volatile("cp.async.commit_group;" ::: "memory")
#define CP_WAIT0()  asm volatile("cp.async.wait_group 0;" ::: "memory")
#define CP_WAIT1()  asm volatile("cp.async.wait_group 1;" ::: "memory")

#define LDMX4(r, addr) \
    asm volatile("ldmatrix.sync.aligned.m8n8.x4.shared.b16 {%0,%1,%2,%3}, [%4];" \
        : "=r"((r)[0]), "=r"((r)[1]), "=r"((r)[2]), "=r"((r)[3]) : "r"(addr))

#define MMA16816(c, a, b0, b1) \
    asm volatile("mma.sync.aligned.m16n8k16.row.col.f32.bf16.bf16.f32 " \
        "{%0,%1,%2,%3}, {%4,%5,%6,%7}, {%8,%9}, {%0,%1,%2,%3};" \
        : "+f"((c)[0]), "+f"((c)[1]), "+f"((c)[2]), "+f"((c)[3]) \
        : "r"((a)[0]), "r"((a)[1]), "r"((a)[2]), "r"((a)[3]), "r"(b0), "r"(b1))

__device__ __forceinline__ void split_bf16(float v, __nv_bfloat16& hi, __nv_bfloat16& lo) {
    hi = __float2bfloat16(v);
    lo = __float2bfloat16(v - __bfloat162float(hi));
}

// ---------------------------------------------------------------------------
// Kernel 0a: prep K — smem-tiled transpose + hi/lo split.
// ---------------------------------------------------------------------------
__global__ __launch_bounds__(256) void prep_k(const float* __restrict__ Kmat)
{
    __shared__ float ts[128 * 33];
    const int r  = blockIdx.x;
    const int nb = blockIdx.y;
    const int tid = threadIdx.x;
#pragma unroll
    for (int j = 0; j < 16; j++) {
        int idx = tid + j * 256;
        int h  = idx >> 5;
        int nc = idx & 31;
        ts[h * 33 + nc] = Kmat[(size_t)h * (HSZ * RSZ) + r * HSZ + nb * 32 + nc];
    }
    __syncthreads();
#pragma unroll
    for (int j = 0; j < 16; j++) {
        int idx = tid + j * 256;
        int nc = idx >> 7;
        int h  = idx & 127;
        float v = ts[h * 33 + nc];
        __nv_bfloat16 hi, lo; split_bf16(v, hi, lo);
        size_t off = (size_t)r * HSZ * HSZ + (size_t)(nb * 32 + nc) * HSZ + h;
        g_KH[off] = hi;
        g_KL[off] = lo;
    }
}

// ---------------------------------------------------------------------------
// Kernel 0b: prep W — transpose Wh/Wt + hi/lo split.
// ---------------------------------------------------------------------------
__global__ __launch_bounds__(256) void prep_w(const float* __restrict__ Wh,
                                              const float* __restrict__ Wt)
{
    __shared__ float tw[32 * 129];
    const int kb = blockIdx.x;
    const int br = blockIdx.y;
    const float* W = br ? Wt : Wh;
    const int tid = threadIdx.x;
#pragma unroll
    for (int j = 0; j < 16; j++) {
        int idx = tid + j * 256;
        int k = idx >> 7;
        int n = idx & 127;
        tw[k * 129 + n] = W[(size_t)(kb * 32 + k) * HSZ + n];
    }
    __syncthreads();
#pragma unroll
    for (int j = 0; j < 16; j++) {
        int idx = tid + j * 256;
        int n = idx >> 5;
        int k = idx & 31;
        float v = tw[k * 129 + n];
        __nv_bfloat16 hi, lo; split_bf16(v, hi, lo);
        size_t off = (size_t)br * HSZ * DSZ + (size_t)n * DSZ + kb * 32 + k;
        g_WH[off] = hi;
        g_WL[off] = lo;
    }
}

// ---------------------------------------------------------------------------
// Kernel 1: dual FF GEMM on tensor cores. 512 threads, warp grid 4x4,
// warp tile 32(M) x 32(N). K=768 in 24 chunks, 2-stage B pipeline.
// ---------------------------------------------------------------------------
#define FFROW 80                                   // bytes per padded row
#define FF_AT (128 * FFROW)                        // 10240 per matrix
#define FF_AH 0
#define FF_AL FF_AT
#define FF_BB (2 * FF_AT)
#define FF_BS (2 * FF_AT)
#define FF_SMEM (FF_BB + 2 * FF_BS)                // 61440

__global__ __launch_bounds__(512) void ff_mma(
    const float* __restrict__ x,
    const float* __restrict__ root,
    const float* __restrict__ bh, const float* __restrict__ bt)
{
    extern __shared__ char sm[];
    const uint32_t sb = smem_u32(sm);

    const int branch = blockIdx.y;
    const int M      = (branch == 0) ? MHEAD : NTOK;
    const int m0     = blockIdx.x * 128;
    if (m0 >= M) return;

    const float* bias = (branch == 0) ? bh : bt;
    const __nv_bfloat16* WH = g_WH + (size_t)branch * HSZ * DSZ;
    const __nv_bfloat16* WL = g_WL + (size_t)branch * HSZ * DSZ;

    const int tid  = threadIdx.x;
    const int lane = tid & 31;
    const int warp = tid >> 5;
    const int wm   = warp >> 2;          // 0..3
    const int wn   = warp & 3;           // 0..3

    // per-thread A rows (2 float4 per chunk)
    const float* arow[2];
    bool rowok[2];
    int rown[2], colf[2];
#pragma unroll
    for (int i = 0; i < 2; i++) {
        int c   = tid + i * 512;
        int row = c >> 3;
        int c4  = c & 7;
        rown[i] = row; colf[i] = c4;
        int g = m0 + row;
        const float* p = nullptr;
        bool ok = (g < M);
        if (ok) {
            if (branch == 0) {
                int b  = g / APP;
                int ii = g - b * APP;
                p = (ii == 0) ? root : (x + (size_t)(b * SSZ + (ii - 1)) * DSZ);
            } else {
                p = x + (size_t)g * DSZ;
            }
        }
        arow[i] = p; rowok[i] = ok;
    }

    auto load_B = [&](uint32_t buf, int k0) {
        int row = tid >> 2;
        int c4  = tid & 3;
        size_t so = (size_t)row * DSZ + k0 + c4 * 8;
        uint32_t d = buf + row * FFROW + c4 * 16;
        CP16(d, WH + so);
        CP16(d + FF_BS / 2, WL + so);
    };

    float4 va[2];
#pragma unroll
    for (int i = 0; i < 2; i++)
        va[i] = rowok[i] ? *(const float4*)(arow[i] + colf[i] * 4)
                         : make_float4(0.f, 0.f, 0.f, 0.f);
    load_B(sb + FF_BB, 0);
    CP_COMMIT();

    float acc[2][4][4];
#pragma unroll
    for (int mt = 0; mt < 2; mt++)
#pragma unroll
        for (int nt = 0; nt < 4; nt++)
#pragma unroll
            for (int e = 0; e < 4; e++) acc[mt][nt][e] = 0.f;

    const uint32_t aLaneOff = (uint32_t)(wm * 32 + (lane & 15)) * FFROW
                            + (uint32_t)(lane >> 4) * 16;
    const uint32_t bLaneOff = (uint32_t)(wn * 32 + (lane & 7) + ((lane >> 4) << 3)) * FFROW
                            + (uint32_t)((lane >> 3) & 1) * 16;

#pragma unroll 1
    for (int ch = 0; ch < 24; ch++) {
        const int nxt = ch + 1;
        if (nxt < 24) load_B(sb + FF_BB + (nxt & 1) * FF_BS, nxt * 32);
        CP_COMMIT();

#pragma unroll
        for (int i = 0; i < 2; i++) {
            __nv_bfloat16 h0, h1, h2, h3, l0, l1, l2, l3;
            split_bf16(va[i].x, h0, l0); split_bf16(va[i].y, h1, l1);
            split_bf16(va[i].z, h2, l2); split_bf16(va[i].w, h3, l3);
            uint32_t hw0 = (uint32_t)__bfloat16_as_ushort(h0) | ((uint32_t)__bfloat16_as_ushort(h1) << 16);
            uint32_t hw1 = (uint32_t)__bfloat16_as_ushort(h2) | ((uint32_t)__bfloat16_as_ushort(h3) << 16);
            uint32_t lw0 = (uint32_t)__bfloat16_as_ushort(l0) | ((uint32_t)__bfloat16_as_ushort(l1) << 16);
            uint32_t lw1 = (uint32_t)__bfloat16_as_ushort(l2) | ((uint32_t)__bfloat16_as_ushort(l3) << 16);
            uint32_t off = rown[i] * FFROW + colf[i] * 8;
            *(uint2*)(sm + FF_AH + off) = make_uint2(hw0, hw1);
            *(uint2*)(sm + FF_AL + off) = make_uint2(lw0, lw1);
        }
        if (nxt < 24) {
#pragma unroll
            for (int i = 0; i < 2; i++)
                va[i] = rowok[i] ? *(const float4*)(arow[i] + nxt * 32 + colf[i] * 4)
                                 : make_float4(0.f, 0.f, 0.f, 0.f);
        }
        CP_WAIT1();
        __syncthreads();

        const uint32_t bufb = sb + FF_BB + (ch & 1) * FF_BS;
#pragma unroll
        for (int pass = 0; pass < 3; pass++) {
            const uint32_t aB = sb + ((pass == 1) ? FF_AL : FF_AH) + aLaneOff;
            const uint32_t bB = bufb + ((pass == 2) ? (FF_BS / 2) : 0) + bLaneOff;
#pragma unroll
            for (int ks = 0; ks < 2; ks++) {
                uint32_t aF[2][4];
#pragma unroll
                for (int mt = 0; mt < 2; mt++)
                    LDMX4(aF[mt], aB + (uint32_t)mt * 16 * FFROW + (uint32_t)ks * 32);
                uint32_t bF[2][4];
#pragma unroll
                for (int np = 0; np < 2; np++)
                    LDMX4(bF[np], bB + (uint32_t)np * 16 * FFROW + (uint32_t)ks * 32);
#pragma unroll
                for (int mt = 0; mt < 2; mt++)
#pragma unroll
                    for (int nt = 0; nt < 4; nt++)
                        MMA16816(acc[mt][nt], aF[mt],
                                 bF[nt >> 1][(nt & 1) * 2], bF[nt >> 1][(nt & 1) * 2 + 1]);
            }
        }
        __syncthreads();
    }

    float2 bv[4];
#pragma unroll
    for (int nt = 0; nt < 4; nt++)
        bv[nt] = *(const float2*)&bias[wn * 32 + nt * 8 + (lane & 3) * 2];

#pragma unroll
    for (int mt = 0; mt < 2; mt++) {
#pragma unroll
        for (int half = 0; half < 2; half++) {
            const int row  = wm * 32 + mt * 16 + (lane >> 2) + half * 8;
            const int grow = m0 + row;
            if (grow >= M) continue;
#pragma unroll
            for (int nt = 0; nt < 4; nt++) {
                const int col = wn * 32 + nt * 8 + (lane & 3) * 2;
                float f0 = fmaxf(acc[mt][nt][half * 2 + 0] + bv[nt].x, 0.f);
                float f1 = fmaxf(acc[mt][nt][half * 2 + 1] + bv[nt].y, 0.f);
                if (branch == 0) {
                    __nv_bfloat16 h0, l0, h1, l1;
                    split_bf16(f0, h0, l0); split_bf16(f1, h1, l1);
                    *(uint32_t*)&g_headH[(size_t)grow * HSZ + col] =
                        (uint32_t)__bfloat16_as_ushort(h0) | ((uint32_t)__bfloat16_as_ushort(h1) << 16);
                    *(uint32_t*)&g_headL[(size_t)grow * HSZ + col] =
                        (uint32_t)__bfloat16_as_ushort(l0) | ((uint32_t)__bfloat16_as_ushort(l1) << 16);
                } else {
                    *(float2*)&g_tail[(size_t)grow * HSZ + col] = make_float2(f0, f1);
                }
            }
        }
    }
}

// ---------------------------------------------------------------------------
// Kernel 2: biaffine, 128 tokens x 4 r per CTA, 512 threads (warp grid 4x4,
// warp tile 32x32). A resident, B double-buffered via cp.async.
// ---------------------------------------------------------------------------
#define APITCH 136
#define TILE_B (128 * APITCH * 2)      // 34816
#define BI_AH 0
#define BI_AL TILE_B
#define BI_BB (2 * TILE_B)             // 69632
#define BI_BS (2 * TILE_B)
#define BI_RED (BI_BB + 2 * BI_BS)     // 208896
#define BI_SMEM (BI_RED + 128 * 4 * 4) // 210944

__global__ __launch_bounds__(512) void biaffine_mma(
    const int* __restrict__ head_id,
    float* __restrict__ out)
{
    extern __shared__ char sm[];
    const uint32_t sb = smem_u32(sm);
    float* red = (float*)(sm + BI_RED);

    const int rg  = blockIdx.x;
    const int t0  = blockIdx.y * 128;
    const int tid = threadIdx.x;
    const int lane = tid & 31;
    const int warp = tid >> 5;
    const int wm = warp >> 2;           // 0..3
    const int wn = warp & 3;            // 0..3

    auto load_B = [&](uint32_t buf, int r) {
        const __nv_bfloat16* srcH = g_KH + (size_t)r * HSZ * HSZ;
        const __nv_bfloat16* srcL = g_KL + (size_t)r * HSZ * HSZ;
#pragma unroll
        for (int i = 0; i < 4; i++) {
            int c   = tid + i * 512;
            int row = c >> 4;
            int col = c & 15;
            uint32_t so = (uint32_t)row * (APITCH * 2) + col * 16;
            size_t go = (size_t)row * HSZ + col * 8;
            CP16(buf + so, srcH + go);
            CP16(buf + TILE_B + so, srcL + go);
        }
    };

    // prologue: A gather + B(r0) + red zero
    {
#pragma unroll
        for (int i = 0; i < 4; i++) {
            int c   = tid + i * 512;
            int row = c >> 4;
            int col = c & 15;
            int t   = t0 + row;
            int hid = head_id[t];
            size_t base = ((size_t)(t >> 10) * APP + hid) * HSZ + col * 8;
            uint32_t so = (uint32_t)row * (APITCH * 2) + col * 16;
            CP16(sb + BI_AH + so, g_headH + base);
            CP16(sb + BI_AL + so, g_headL + base);
        }
        load_B(sb + BI_BB, rg * 4);
        if (tid < 128) *(float4*)&red[tid * 4] = make_float4(0.f, 0.f, 0.f, 0.f);
        CP_COMMIT();
    }

    const uint32_t aLaneOff = (uint32_t)(wm * 32 + (lane & 15)) * (APITCH * 2)
                            + (uint32_t)(lane >> 4) * 16;
    const uint32_t bLaneOff = (uint32_t)(wn * 32 + (lane & 7) + ((lane >> 4) << 3)) * (APITCH * 2)
                            + (uint32_t)((lane >> 3) & 1) * 16;

#pragma unroll 1
    for (int i = 0; i < 4; i++) {
        if (i < 3) load_B(sb + BI_BB + ((i + 1) & 1) * BI_BS, rg * 4 + i + 1);
        CP_COMMIT();
        CP_WAIT1();
        __syncthreads();

        float acc[2][4][4];
#pragma unroll
        for (int mt = 0; mt < 2; mt++)
#pragma unroll
            for (int nt = 0; nt < 4; nt++)
#pragma unroll
                for (int e = 0; e < 4; e++) acc[mt][nt][e] = 0.f;

        const uint32_t bufb = sb + BI_BB + (i & 1) * BI_BS;
#pragma unroll
        for (int pass = 0; pass < 3; pass++) {
            const uint32_t aB = sb + ((pass == 1) ? BI_AL : BI_AH) + aLaneOff;
            const uint32_t bB = bufb + ((pass == 2) ? TILE_B : 0) + bLaneOff;
#pragma unroll
            for (int k = 0; k < 8; k++) {
                uint32_t aF[2][4];
#pragma unroll
                for (int mt = 0; mt < 2; mt++)
                    LDMX4(aF[mt], aB + (uint32_t)mt * 16 * (APITCH * 2) + (uint32_t)k * 32);
                uint32_t bF[2][4];
#pragma unroll
                for (int np = 0; np < 2; np++)
                    LDMX4(bF[np], bB + (uint32_t)np * 16 * (APITCH * 2) + (uint32_t)k * 32);
#pragma unroll
                for (int mt = 0; mt < 2; mt++)
#pragma unroll
                    for (int nt = 0; nt < 4; nt++)
                        MMA16816(acc[mt][nt], aF[mt],
                                 bF[nt >> 1][(nt & 1) * 2], bF[nt >> 1][(nt & 1) * 2 + 1]);
            }
        }

        // epilogue: dot with tail, quad-reduce, accumulate into red[:,i]
#pragma unroll
        for (int mt = 0; mt < 2; mt++) {
#pragma unroll
            for (int half = 0; half < 2; half++) {
                const int lrow = wm * 32 + mt * 16 + (lane >> 2) + half * 8;
                const int t    = t0 + lrow;
                float p = 0.f;
#pragma unroll
                for (int nt = 0; nt < 4; nt++) {
                    const int col = wn * 32 + nt * 8 + (lane & 3) * 2;
                    float2 tl = *(const float2*)&g_tail[(size_t)t * HSZ + col];
                    p += acc[mt][nt][half * 2 + 0] * tl.x
                       + acc[mt][nt][half * 2 + 1] * tl.y;
                }
                p += __shfl_xor_sync(0xffffffffu, p, 1);
                p += __shfl_xor_sync(0xffffffffu, p, 2);
                if ((lane & 3) == 0) atomicAdd(&red[lrow * 4 + i], p);
            }
        }
        __syncthreads();
    }

    if (tid < 128) {
        float4 v = *(float4*)&red[tid * 4];
        *(float4*)&out[(size_t)(t0 + tid) * RSZ + rg * 4] = v;
    }
}

// ---------------------------------------------------------------------------
extern "C" void kernel_launch(void* const* d_in, const int* in_sizes, int n_in,
                              void* d_out, int out_size)
{
    const float* x       = (const float*)d_in[0];
    const int*   head_id = (const int*)  d_in[1];
    const float* root    = (const float*)d_in[2];
    const float* Wh      = (const float*)d_in[3];
    const float* bh      = (const float*)d_in[4];
    const float* Wt      = (const float*)d_in[5];
    const float* bt      = (const float*)d_in[6];
    const float* Kmat    = (const float*)d_in[7];
    float*       out     = (float*)d_out;

    prep_k<<<dim3(RSZ, 4), 256>>>(Kmat);
    prep_w<<<dim3(24, 2), 256>>>(Wh, Wt);

    cudaFuncSetAttribute(ff_mma, cudaFuncAttributeMaxDynamicSharedMemorySize, FF_SMEM);
    ff_mma<<<dim3(257, 2), 512, FF_SMEM>>>(x, root, bh, bt);

    cudaFuncSetAttribute(biaffine_mma, cudaFuncAttributeMaxDynamicSharedMemorySize, BI_SMEM);
    biaffine_mma<<<dim3(RSZ / 4, NTOK / 128), 512, BI_SMEM>>>(head_id, out);
}

// round 6
// speedup vs baseline: 1.2285x; 1.2285x over previous
#include <cuda_runtime.h>
#include <cuda_bf16.h>
#include <cstdint>

// Problem constants
#define BSZ   32
#define SSZ   1024
#define DSZ   768
#define HSZ   128
#define RSZ   48
#define APP   (SSZ + 1)        // 1025
#define NTOK  (BSZ * SSZ)      // 32768
#define MHEAD (BSZ * APP)      // 32800

// Scratch (device globals)
__device__ __nv_bfloat16 g_headH[(size_t)MHEAD * HSZ];
__device__ __nv_bfloat16 g_headL[(size_t)MHEAD * HSZ];
__device__ float         g_tail [(size_t)NTOK * HSZ];
__device__ __nv_bfloat16 g_WH[(size_t)2 * HSZ * DSZ];     // W^T [branch][n][k] hi
__device__ __nv_bfloat16 g_WL[(size_t)2 * HSZ * DSZ];     // W^T [branch][n][k] lo
// Fragment-ordered B image per r: [r][part(hi=0,lo=1)][ks(8)][g(8)][lane(32)][16B]
// uint4 units: r*4096 + part*2048 + ks*256 + g*32 + lane
__device__ uint4 g_Bfrag[(size_t)RSZ * 4096];

// ---------------------------------------------------------------------------
// PTX helpers (target-suffix-free)
// ---------------------------------------------------------------------------
__device__ __forceinline__ uint32_t smem_u32(const void* p) {
    uint32_t a;
    asm("{ .reg .u64 t; cvta.to.shared.u64 t, %1; cvt.u32.u64 %0, t; }" : "=r"(a) : "l"(p));
    return a;
}

#define CP16(dst, src) \
    asm volatile("cp.async.cg.shared.global [%0], [%1], 16;" :: "r"(dst), "l"(src) : "memory")
#define CP_COMMIT() asm volatile("cp.async.commit_group;" ::: "memory")
#define CP_WAIT0()  asm volatile("cp.async.wait_group 0;" ::: "memory")
#define CP_WAIT1()  asm volatile("cp.async.wait_group 1;" ::: "memory")

#define LDMX4(r, addr) \
    asm volatile("ldmatrix.sync.aligned.m8n8.x4.shared.b16 {%0,%1,%2,%3}, [%4];" \
        : "=r"((r)[0]), "=r"((r)[1]), "=r"((r)[2]), "=r"((r)[3]) : "r"(addr))

#define MMA16816(c, a, b0, b1) \
    asm volatile("mma.sync.aligned.m16n8k16.row.col.f32.bf16.bf16.f32 " \
        "{%0,%1,%2,%3}, {%4,%5,%6,%7}, {%8,%9}, {%0,%1,%2,%3};" \
        : "+f"((c)[0]), "+f"((c)[1]), "+f"((c)[2]), "+f"((c)[3]) \
        : "r"((a)[0]), "r"((a)[1]), "r"((a)[2]), "r"((a)[3]), "r"(b0), "r"(b1))

__device__ __forceinline__ void split_bf16(float v, __nv_bfloat16& hi, __nv_bfloat16& lo) {
    hi = __float2bfloat16(v);
    lo = __float2bfloat16(v - __bfloat162float(hi));
}
__device__ __forceinline__ uint32_t pack_bf16(__nv_bfloat16 a, __nv_bfloat16 b) {
    return (uint32_t)__bfloat16_as_ushort(a) | ((uint32_t)__bfloat16_as_ushort(b) << 16);
}

// ---------------------------------------------------------------------------
// Kernel 0a: prep K -> fragment-ordered hi/lo B images.
//   For r: B_r fragment unit (uint32 index v within 8192-per-part):
//     v = ks*1024 + g*128 + lane*4 + hw2, hw2: pair=hw2>>1, reg=hw2&1
//     n = (2g+pair)*8 + (lane>>2); h0 = ks*16 + reg*8 + (lane&3)*2 (elements h0,h0+1)
// ---------------------------------------------------------------------------
__global__ __launch_bounds__(256) void prep_k(const float* __restrict__ Kmat)
{
    extern __shared__ float ksm[];           // [128][129]
    const int r   = blockIdx.x;
    const int tid = threadIdx.x;
    // stage K_r: smem[h][n] = K[h, r*128+n] (coalesced over n)
#pragma unroll
    for (int j = 0; j < 64; j++) {
        int idx = tid + j * 256;             // 16384
        int h = idx >> 7, n = idx & 127;
        ksm[h * 129 + n] = Kmat[(size_t)h * (HSZ * RSZ) + r * HSZ + n];
    }
    __syncthreads();

    uint32_t* outH = (uint32_t*)(g_Bfrag + (size_t)r * 4096);
    uint32_t* outL = outH + 8192;
#pragma unroll
    for (int j = 0; j < 32; j++) {
        int v = tid + j * 256;               // 0..8191
        int ks   = v >> 10;
        int rem  = v & 1023;
        int g    = rem >> 7;
        int rem2 = rem & 127;
        int lane = rem2 >> 2;
        int hw2  = rem2 & 3;
        int pair = hw2 >> 1, reg = hw2 & 1;
        int n  = (2 * g + pair) * 8 + (lane >> 2);
        int h0 = ks * 16 + reg * 8 + (lane & 3) * 2;
        float f0 = ksm[h0 * 129 + n];
        float f1 = ksm[(h0 + 1) * 129 + n];
        __nv_bfloat16 h_0, l_0, h_1, l_1;
        split_bf16(f0, h_0, l_0);
        split_bf16(f1, h_1, l_1);
        outH[v] = pack_bf16(h_0, h_1);
        outL[v] = pack_bf16(l_0, l_1);
    }
}

// ---------------------------------------------------------------------------
// Kernel 0b: prep W — transpose Wh/Wt + hi/lo split.
// ---------------------------------------------------------------------------
__global__ __launch_bounds__(256) void prep_w(const float* __restrict__ Wh,
                                              const float* __restrict__ Wt)
{
    __shared__ float tw[32 * 129];
    const int kb = blockIdx.x;
    const int br = blockIdx.y;
    const float* W = br ? Wt : Wh;
    const int tid = threadIdx.x;
#pragma unroll
    for (int j = 0; j < 16; j++) {
        int idx = tid + j * 256;
        int k = idx >> 7;
        int n = idx & 127;
        tw[k * 129 + n] = W[(size_t)(kb * 32 + k) * HSZ + n];
    }
    __syncthreads();
#pragma unroll
    for (int j = 0; j < 16; j++) {
        int idx = tid + j * 256;
        int n = idx >> 5;
        int k = idx & 31;
        float v = tw[k * 129 + n];
        __nv_bfloat16 hi, lo; split_bf16(v, hi, lo);
        size_t off = (size_t)br * HSZ * DSZ + (size_t)n * DSZ + kb * 32 + k;
        g_WH[off] = hi;
        g_WL[off] = lo;
    }
}

// ---------------------------------------------------------------------------
// Kernel 1: dual FF GEMM on tensor cores (R4 proven config: 256 thr, 2x4 warps,
// warp tile 64x32, K=768 in 24 chunks, 2-stage B pipeline).
// ---------------------------------------------------------------------------
#define FFROW 80
#define FF_AT (128 * FFROW)
#define FF_AH 0
#define FF_AL FF_AT
#define FF_BB (2 * FF_AT)
#define FF_BS (2 * FF_AT)
#define FF_SMEM (FF_BB + 2 * FF_BS)                // 61440

__global__ __launch_bounds__(256) void ff_mma(
    const float* __restrict__ x,
    const float* __restrict__ root,
    const float* __restrict__ bh, const float* __restrict__ bt)
{
    extern __shared__ char sm[];
    const uint32_t sb = smem_u32(sm);

    const int branch = blockIdx.y;
    const int M      = (branch == 0) ? MHEAD : NTOK;
    const int m0     = blockIdx.x * 128;
    if (m0 >= M) return;

    const float* bias = (branch == 0) ? bh : bt;
    const __nv_bfloat16* WH = g_WH + (size_t)branch * HSZ * DSZ;
    const __nv_bfloat16* WL = g_WL + (size_t)branch * HSZ * DSZ;

    const int tid  = threadIdx.x;
    const int lane = tid & 31;
    const int warp = tid >> 5;
    const int wm   = warp >> 2;
    const int wn   = warp & 3;

    const float* arow[4];
    bool rowok[4];
    int rown[4], colf[4];
#pragma unroll
    for (int i = 0; i < 4; i++) {
        int c   = tid + i * 256;
        int row = c >> 3;
        int c4  = c & 7;
        rown[i] = row; colf[i] = c4;
        int g = m0 + row;
        const float* p = nullptr;
        bool ok = (g < M);
        if (ok) {
            if (branch == 0) {
                int b  = g / APP;
                int ii = g - b * APP;
                p = (ii == 0) ? root : (x + (size_t)(b * SSZ + (ii - 1)) * DSZ);
            } else {
                p = x + (size_t)g * DSZ;
            }
        }
        arow[i] = p; rowok[i] = ok;
    }

    auto load_B = [&](uint32_t buf, int k0) {
#pragma unroll
        for (int i = 0; i < 2; i++) {
            int c   = tid + i * 256;
            int row = c >> 2;
            int c4  = c & 3;
            size_t so = (size_t)row * DSZ + k0 + c4 * 8;
            uint32_t d = buf + row * FFROW + c4 * 16;
            CP16(d, WH + so);
            CP16(d + FF_BS / 2, WL + so);
        }
    };

    float4 va[4];
#pragma unroll
    for (int i = 0; i < 4; i++)
        va[i] = rowok[i] ? *(const float4*)(arow[i] + colf[i] * 4)
                         : make_float4(0.f, 0.f, 0.f, 0.f);
    load_B(sb + FF_BB, 0);
    CP_COMMIT();

    float acc[4][4][4];
#pragma unroll
    for (int mt = 0; mt < 4; mt++)
#pragma unroll
        for (int nt = 0; nt < 4; nt++)
#pragma unroll
            for (int e = 0; e < 4; e++) acc[mt][nt][e] = 0.f;

    const uint32_t aLaneOff = (uint32_t)(wm * 64 + (lane & 15)) * FFROW
                            + (uint32_t)(lane >> 4) * 16;
    const uint32_t bLaneOff = (uint32_t)(wn * 32 + (lane & 7) + ((lane >> 4) << 3)) * FFROW
                            + (uint32_t)((lane >> 3) & 1) * 16;

#pragma unroll 1
    for (int ch = 0; ch < 24; ch++) {
        const int nxt = ch + 1;
        if (nxt < 24) load_B(sb + FF_BB + (nxt & 1) * FF_BS, nxt * 32);
        CP_COMMIT();

#pragma unroll
        for (int i = 0; i < 4; i++) {
            __nv_bfloat16 h0, h1, h2, h3, l0, l1, l2, l3;
            split_bf16(va[i].x, h0, l0); split_bf16(va[i].y, h1, l1);
            split_bf16(va[i].z, h2, l2); split_bf16(va[i].w, h3, l3);
            uint32_t off = rown[i] * FFROW + colf[i] * 8;
            *(uint2*)(sm + FF_AH + off) = make_uint2(pack_bf16(h0, h1), pack_bf16(h2, h3));
            *(uint2*)(sm + FF_AL + off) = make_uint2(pack_bf16(l0, l1), pack_bf16(l2, l3));
        }
        if (nxt < 24) {
#pragma unroll
            for (int i = 0; i < 4; i++)
                va[i] = rowok[i] ? *(const float4*)(arow[i] + nxt * 32 + colf[i] * 4)
                                 : make_float4(0.f, 0.f, 0.f, 0.f);
        }
        CP_WAIT1();
        __syncthreads();

        const uint32_t bufb = sb + FF_BB + (ch & 1) * FF_BS;
#pragma unroll
        for (int pass = 0; pass < 3; pass++) {
            const uint32_t aB = sb + ((pass == 1) ? FF_AL : FF_AH) + aLaneOff;
            const uint32_t bB = bufb + ((pass == 2) ? (FF_BS / 2) : 0) + bLaneOff;
#pragma unroll
            for (int ks = 0; ks < 2; ks++) {
                uint32_t aF[4][4];
#pragma unroll
                for (int mt = 0; mt < 4; mt++)
                    LDMX4(aF[mt], aB + (uint32_t)mt * 16 * FFROW + (uint32_t)ks * 32);
                uint32_t bF[2][4];
#pragma unroll
                for (int np = 0; np < 2; np++)
                    LDMX4(bF[np], bB + (uint32_t)np * 16 * FFROW + (uint32_t)ks * 32);
#pragma unroll
                for (int mt = 0; mt < 4; mt++)
#pragma unroll
                    for (int nt = 0; nt < 4; nt++)
                        MMA16816(acc[mt][nt], aF[mt],
                                 bF[nt >> 1][(nt & 1) * 2], bF[nt >> 1][(nt & 1) * 2 + 1]);
            }
        }
        __syncthreads();
    }

    float2 bv[4];
#pragma unroll
    for (int nt = 0; nt < 4; nt++)
        bv[nt] = *(const float2*)&bias[wn * 32 + nt * 8 + (lane & 3) * 2];

#pragma unroll
    for (int mt = 0; mt < 4; mt++) {
#pragma unroll
        for (int half = 0; half < 2; half++) {
            const int row  = wm * 64 + mt * 16 + (lane >> 2) + half * 8;
            const int grow = m0 + row;
            if (grow >= M) continue;
#pragma unroll
            for (int nt = 0; nt < 4; nt++) {
                const int col = wn * 32 + nt * 8 + (lane & 3) * 2;
                float f0 = fmaxf(acc[mt][nt][half * 2 + 0] + bv[nt].x, 0.f);
                float f1 = fmaxf(acc[mt][nt][half * 2 + 1] + bv[nt].y, 0.f);
                if (branch == 0) {
                    __nv_bfloat16 h0, l0, h1, l1;
                    split_bf16(f0, h0, l0); split_bf16(f1, h1, l1);
                    *(uint32_t*)&g_headH[(size_t)grow * HSZ + col] = pack_bf16(h0, h1);
                    *(uint32_t*)&g_headL[(size_t)grow * HSZ + col] = pack_bf16(l0, l1);
                } else {
                    *(float2*)&g_tail[(size_t)grow * HSZ + col] = make_float2(f0, f1);
                }
            }
        }
    }
}

// ---------------------------------------------------------------------------
// Kernel 2: biaffine v3. CTA = 128 tokens x 24 r. 256 threads, 8 warps,
// warp tile m16 x n128. A (head hi/lo) resident in smem (ldmatrix);
// B streamed as LDG.128 fragments from g_Bfrag (L1/L2-resident);
// epilogue fully warp-local (quad shfl + direct STG). No mainloop barriers.
// ---------------------------------------------------------------------------
#define AROW 272                       // bytes per A smem row (136 bf16)
#define ATILE (128 * AROW)             // 34816 per matrix
#define BI_SMEM (2 * ATILE)            // 69632

__global__ __launch_bounds__(256, 2) void biaffine_mma(
    const int* __restrict__ head_id,
    float* __restrict__ out)
{
    extern __shared__ char sm[];
    const uint32_t sb = smem_u32(sm);

    const int t0  = blockIdx.x * 128;
    const int r0  = blockIdx.y * 24;
    const int tid = threadIdx.x;
    const int lane = tid & 31;
    const int warp = tid >> 5;

    // A gather: 128 rows x 16 chunks(16B) per matrix, 8 chunks per thread each
#pragma unroll
    for (int i = 0; i < 8; i++) {
        int c   = tid + i * 256;
        int row = c >> 4;
        int col = c & 15;
        int t   = t0 + row;
        int hid = head_id[t];
        size_t base = ((size_t)(t >> 10) * APP + hid) * HSZ + col * 8;
        uint32_t so = (uint32_t)row * AROW + col * 16;
        CP16(sb + so, g_headH + base);
        CP16(sb + ATILE + so, g_headL + base);
    }
    CP_COMMIT();
    CP_WAIT0();
    __syncthreads();

    const uint32_t aAddrH = sb + (uint32_t)(warp * 16 + (lane & 15)) * AROW
                          + (uint32_t)(lane >> 4) * 16;
    const uint32_t aAddrL = aAddrH + ATILE;

    // epilogue address prep
    const int trow_lo = t0 + warp * 16 + (lane >> 2);
    const int trow_hi = trow_lo + 8;
    const float* tl = g_tail + (size_t)trow_lo * HSZ + (lane & 3) * 2;
    const float* th = g_tail + (size_t)trow_hi * HSZ + (lane & 3) * 2;

#pragma unroll 1
    for (int rr = 0; rr < 24; rr++) {
        const int r = r0 + rr;
        const uint4* __restrict__ bF = g_Bfrag + (size_t)r * 4096 + lane;

        float acc[16][4];
#pragma unroll
        for (int nb = 0; nb < 16; nb++)
#pragma unroll
            for (int e = 0; e < 4; e++) acc[nb][e] = 0.f;

        // fused pass: Ah*Bh + Al*Bh
#pragma unroll
        for (int ks = 0; ks < 8; ks++) {
            uint32_t aH[4], aL[4];
            LDMX4(aH, aAddrH + ks * 32);
            LDMX4(aL, aAddrL + ks * 32);
            const uint4* bk = bF + ks * 256;
#pragma unroll
            for (int g = 0; g < 8; g++) {
                uint4 bv = bk[g * 32];
                MMA16816(acc[2 * g],     aH, bv.x, bv.y);
                MMA16816(acc[2 * g + 1], aH, bv.z, bv.w);
                MMA16816(acc[2 * g],     aL, bv.x, bv.y);
                MMA16816(acc[2 * g + 1], aL, bv.z, bv.w);
            }
        }
        // pass: Ah*Bl
#pragma unroll
        for (int ks = 0; ks < 8; ks++) {
            uint32_t aH[4];
            LDMX4(aH, aAddrH + ks * 32);
            const uint4* bk = bF + 2048 + ks * 256;
#pragma unroll
            for (int g = 0; g < 8; g++) {
                uint4 bv = bk[g * 32];
                MMA16816(acc[2 * g],     aH, bv.x, bv.y);
                MMA16816(acc[2 * g + 1], aH, bv.z, bv.w);
            }
        }

        // warp-local epilogue: out[t,r] = sum_k P[t,k]*tail[t,k]
        float plo = 0.f, phi = 0.f;
#pragma unroll
        for (int nb = 0; nb < 16; nb++) {
            float2 a = *(const float2*)(tl + nb * 8);
            float2 b = *(const float2*)(th + nb * 8);
            plo += acc[nb][0] * a.x + acc[nb][1] * a.y;
            phi += acc[nb][2] * b.x + acc[nb][3] * b.y;
        }
        plo += __shfl_xor_sync(0xffffffffu, plo, 1);
        plo += __shfl_xor_sync(0xffffffffu, plo, 2);
        phi += __shfl_xor_sync(0xffffffffu, phi, 1);
        phi += __shfl_xor_sync(0xffffffffu, phi, 2);
        if ((lane & 3) == 0) {
            out[(size_t)trow_lo * RSZ + r] = plo;
            out[(size_t)trow_hi * RSZ + r] = phi;
        }
    }
}

// ---------------------------------------------------------------------------
extern "C" void kernel_launch(void* const* d_in, const int* in_sizes, int n_in,
                              void* d_out, int out_size)
{
    const float* x       = (const float*)d_in[0];
    const int*   head_id = (const int*)  d_in[1];
    const float* root    = (const float*)d_in[2];
    const float* Wh      = (const float*)d_in[3];
    const float* bh      = (const float*)d_in[4];
    const float* Wt      = (const float*)d_in[5];
    const float* bt      = (const float*)d_in[6];
    const float* Kmat    = (const float*)d_in[7];
    float*       out     = (float*)d_out;

    const int prep_smem = 128 * 129 * sizeof(float);   // 66048
    cudaFuncSetAttribute(prep_k, cudaFuncAttributeMaxDynamicSharedMemorySize, prep_smem);
    prep_k<<<RSZ, 256, prep_smem>>>(Kmat);
    prep_w<<<dim3(24, 2), 256>>>(Wh, Wt);

    cudaFuncSetAttribute(ff_mma, cudaFuncAttributeMaxDynamicSharedMemorySize, FF_SMEM);
    ff_mma<<<dim3(257, 2), 256, FF_SMEM>>>(x, root, bh, bt);

    cudaFuncSetAttribute(biaffine_mma, cudaFuncAttributeMaxDynamicSharedMemorySize, BI_SMEM);
    biaffine_mma<<<dim3(NTOK / 128, 2), 256, BI_SMEM>>>(head_id, out);
}

// round 7
// speedup vs baseline: 1.8660x; 1.5190x over previous
#include <cuda_runtime.h>
#include <cuda_bf16.h>
#include <cuda_fp16.h>
#include <cstdint>

// Problem constants
#define BSZ   32
#define SSZ   1024
#define DSZ   768
#define HSZ   128
#define RSZ   48
#define APP   (SSZ + 1)        // 1025
#define NTOK  (BSZ * SSZ)      // 32768
#define MHEAD (BSZ * APP)      // 32800

// Scratch (device globals)
__device__ __half g_headH[(size_t)MHEAD * HSZ];           // fp16 hi of relu head
__device__ __half g_headL[(size_t)MHEAD * HSZ];           // fp16 lo residual
__device__ float  g_tail [(size_t)NTOK * HSZ];
__device__ __nv_bfloat16 g_WH[(size_t)2 * HSZ * DSZ];     // W^T [branch][n][k] hi (bf16)
__device__ __nv_bfloat16 g_WL[(size_t)2 * HSZ * DSZ];     // W^T lo
// Fragment-ordered fp16 B image per r: uint4 units: r*2048 + ks*256 + g*32 + lane
__device__ uint4 g_Bfrag[(size_t)RSZ * 2048];

// ---------------------------------------------------------------------------
// PTX helpers (target-suffix-free)
// ---------------------------------------------------------------------------
__device__ __forceinline__ uint32_t smem_u32(const void* p) {
    uint32_t a;
    asm("{ .reg .u64 t; cvta.to.shared.u64 t, %1; cvt.u32.u64 %0, t; }" : "=r"(a) : "l"(p));
    return a;
}

#define CP16(dst, src) \
    asm volatile("cp.async.cg.shared.global [%0], [%1], 16;" :: "r"(dst), "l"(src) : "memory")
#define CP_COMMIT() asm volatile("cp.async.commit_group;" ::: "memory")
#define CP_WAIT0()  asm volatile("cp.async.wait_group 0;" ::: "memory")
#define CP_WAIT1()  asm volatile("cp.async.wait_group 1;" ::: "memory")

#define LDMX4(r, addr) \
    asm volatile("ldmatrix.sync.aligned.m8n8.x4.shared.b16 {%0,%1,%2,%3}, [%4];" \
        : "=r"((r)[0]), "=r"((r)[1]), "=r"((r)[2]), "=r"((r)[3]) : "r"(addr))

// bf16 MMA (ff kernel)
#define MMA_BF(c, a, b0, b1) \
    asm volatile("mma.sync.aligned.m16n8k16.row.col.f32.bf16.bf16.f32 " \
        "{%0,%1,%2,%3}, {%4,%5,%6,%7}, {%8,%9}, {%0,%1,%2,%3};" \
        : "+f"((c)[0]), "+f"((c)[1]), "+f"((c)[2]), "+f"((c)[3]) \
        : "r"((a)[0]), "r"((a)[1]), "r"((a)[2]), "r"((a)[3]), "r"(b0), "r"(b1))

// fp16 MMA (biaffine kernel)
#define MMA_FP(c, a, b0, b1) \
    asm volatile("mma.sync.aligned.m16n8k16.row.col.f32.f16.f16.f32 " \
        "{%0,%1,%2,%3}, {%4,%5,%6,%7}, {%8,%9}, {%0,%1,%2,%3};" \
        : "+f"((c)[0]), "+f"((c)[1]), "+f"((c)[2]), "+f"((c)[3]) \
        : "r"((a)[0]), "r"((a)[1]), "r"((a)[2]), "r"((a)[3]), "r"(b0), "r"(b1))

__device__ __forceinline__ void split_bf16(float v, __nv_bfloat16& hi, __nv_bfloat16& lo) {
    hi = __float2bfloat16(v);
    lo = __float2bfloat16(v - __bfloat162float(hi));
}
__device__ __forceinline__ void split_fp16(float v, __half& hi, __half& lo) {
    hi = __float2half_rn(v);
    lo = __float2half_rn(v - __half2float(hi));
}
__device__ __forceinline__ uint32_t pack_bf16(__nv_bfloat16 a, __nv_bfloat16 b) {
    return (uint32_t)__bfloat16_as_ushort(a) | ((uint32_t)__bfloat16_as_ushort(b) << 16);
}
__device__ __forceinline__ uint32_t pack_fp16(__half a, __half b) {
    return (uint32_t)__half_as_ushort(a) | ((uint32_t)__half_as_ushort(b) << 16);
}

// ---------------------------------------------------------------------------
// Kernel 0a: prep K -> fragment-ordered fp16 B images (hi only).
//   uint32 index v in [0, 8192): v = ks*1024 + g*128 + lane*4 + hw2
//     pair = hw2>>1, reg = hw2&1
//     n = (2g+pair)*8 + (lane>>2); h0 = ks*16 + reg*8 + (lane&3)*2
// ---------------------------------------------------------------------------
__global__ __launch_bounds__(256) void prep_k(const float* __restrict__ Kmat)
{
    extern __shared__ float ksm[];           // [128][129]
    const int r   = blockIdx.x;
    const int tid = threadIdx.x;
#pragma unroll
    for (int j = 0; j < 64; j++) {
        int idx = tid + j * 256;
        int h = idx >> 7, n = idx & 127;
        ksm[h * 129 + n] = Kmat[(size_t)h * (HSZ * RSZ) + r * HSZ + n];
    }
    __syncthreads();

    uint32_t* outH = (uint32_t*)(g_Bfrag + (size_t)r * 2048);
#pragma unroll
    for (int j = 0; j < 32; j++) {
        int v = tid + j * 256;               // 0..8191
        int ks   = v >> 10;
        int rem  = v & 1023;
        int g    = rem >> 7;
        int rem2 = rem & 127;
        int lane = rem2 >> 2;
        int hw2  = rem2 & 3;
        int pair = hw2 >> 1, reg = hw2 & 1;
        int n  = (2 * g + pair) * 8 + (lane >> 2);
        int h0 = ks * 16 + reg * 8 + (lane & 3) * 2;
        float f0 = ksm[h0 * 129 + n];
        float f1 = ksm[(h0 + 1) * 129 + n];
        outH[v] = pack_fp16(__float2half_rn(f0), __float2half_rn(f1));
    }
}

// ---------------------------------------------------------------------------
// Kernel 0b: prep W — transpose Wh/Wt + bf16 hi/lo split.
// ---------------------------------------------------------------------------
__global__ __launch_bounds__(256) void prep_w(const float* __restrict__ Wh,
                                              const float* __restrict__ Wt)
{
    __shared__ float tw[32 * 129];
    const int kb = blockIdx.x;
    const int br = blockIdx.y;
    const float* W = br ? Wt : Wh;
    const int tid = threadIdx.x;
#pragma unroll
    for (int j = 0; j < 16; j++) {
        int idx = tid + j * 256;
        int k = idx >> 7;
        int n = idx & 127;
        tw[k * 129 + n] = W[(size_t)(kb * 32 + k) * HSZ + n];
    }
    __syncthreads();
#pragma unroll
    for (int j = 0; j < 16; j++) {
        int idx = tid + j * 256;
        int n = idx >> 5;
        int k = idx & 31;
        float v = tw[k * 129 + n];
        __nv_bfloat16 hi, lo; split_bf16(v, hi, lo);
        size_t off = (size_t)br * HSZ * DSZ + (size_t)n * DSZ + kb * 32 + k;
        g_WH[off] = hi;
        g_WL[off] = lo;
    }
}

// ---------------------------------------------------------------------------
// Kernel 1: dual FF GEMM, bf16 3-pass (unchanged proven config).
// Branch-0 epilogue emits fp16 hi/lo head for the biaffine stage.
// ---------------------------------------------------------------------------
#define FFROW 80
#define FF_AT (128 * FFROW)
#define FF_AH 0
#define FF_AL FF_AT
#define FF_BB (2 * FF_AT)
#define FF_BS (2 * FF_AT)
#define FF_SMEM (FF_BB + 2 * FF_BS)                // 61440

__global__ __launch_bounds__(256) void ff_mma(
    const float* __restrict__ x,
    const float* __restrict__ root,
    const float* __restrict__ bh, const float* __restrict__ bt)
{
    extern __shared__ char sm[];
    const uint32_t sb = smem_u32(sm);

    const int branch = blockIdx.y;
    const int M      = (branch == 0) ? MHEAD : NTOK;
    const int m0     = blockIdx.x * 128;
    if (m0 >= M) return;

    const float* bias = (branch == 0) ? bh : bt;
    const __nv_bfloat16* WH = g_WH + (size_t)branch * HSZ * DSZ;
    const __nv_bfloat16* WL = g_WL + (size_t)branch * HSZ * DSZ;

    const int tid  = threadIdx.x;
    const int lane = tid & 31;
    const int warp = tid >> 5;
    const int wm   = warp >> 2;
    const int wn   = warp & 3;

    const float* arow[4];
    bool rowok[4];
    int rown[4], colf[4];
#pragma unroll
    for (int i = 0; i < 4; i++) {
        int c   = tid + i * 256;
        int row = c >> 3;
        int c4  = c & 7;
        rown[i] = row; colf[i] = c4;
        int g = m0 + row;
        const float* p = nullptr;
        bool ok = (g < M);
        if (ok) {
            if (branch == 0) {
                int b  = g / APP;
                int ii = g - b * APP;
                p = (ii == 0) ? root : (x + (size_t)(b * SSZ + (ii - 1)) * DSZ);
            } else {
                p = x + (size_t)g * DSZ;
            }
        }
        arow[i] = p; rowok[i] = ok;
    }

    auto load_B = [&](uint32_t buf, int k0) {
#pragma unroll
        for (int i = 0; i < 2; i++) {
            int c   = tid + i * 256;
            int row = c >> 2;
            int c4  = c & 3;
            size_t so = (size_t)row * DSZ + k0 + c4 * 8;
            uint32_t d = buf + row * FFROW + c4 * 16;
            CP16(d, WH + so);
            CP16(d + FF_BS / 2, WL + so);
        }
    };

    float4 va[4];
#pragma unroll
    for (int i = 0; i < 4; i++)
        va[i] = rowok[i] ? *(const float4*)(arow[i] + colf[i] * 4)
                         : make_float4(0.f, 0.f, 0.f, 0.f);
    load_B(sb + FF_BB, 0);
    CP_COMMIT();

    float acc[4][4][4];
#pragma unroll
    for (int mt = 0; mt < 4; mt++)
#pragma unroll
        for (int nt = 0; nt < 4; nt++)
#pragma unroll
            for (int e = 0; e < 4; e++) acc[mt][nt][e] = 0.f;

    const uint32_t aLaneOff = (uint32_t)(wm * 64 + (lane & 15)) * FFROW
                            + (uint32_t)(lane >> 4) * 16;
    const uint32_t bLaneOff = (uint32_t)(wn * 32 + (lane & 7) + ((lane >> 4) << 3)) * FFROW
                            + (uint32_t)((lane >> 3) & 1) * 16;

#pragma unroll 1
    for (int ch = 0; ch < 24; ch++) {
        const int nxt = ch + 1;
        if (nxt < 24) load_B(sb + FF_BB + (nxt & 1) * FF_BS, nxt * 32);
        CP_COMMIT();

#pragma unroll
        for (int i = 0; i < 4; i++) {
            __nv_bfloat16 h0, h1, h2, h3, l0, l1, l2, l3;
            split_bf16(va[i].x, h0, l0); split_bf16(va[i].y, h1, l1);
            split_bf16(va[i].z, h2, l2); split_bf16(va[i].w, h3, l3);
            uint32_t off = rown[i] * FFROW + colf[i] * 8;
            *(uint2*)(sm + FF_AH + off) = make_uint2(pack_bf16(h0, h1), pack_bf16(h2, h3));
            *(uint2*)(sm + FF_AL + off) = make_uint2(pack_bf16(l0, l1), pack_bf16(l2, l3));
        }
        if (nxt < 24) {
#pragma unroll
            for (int i = 0; i < 4; i++)
                va[i] = rowok[i] ? *(const float4*)(arow[i] + nxt * 32 + colf[i] * 4)
                                 : make_float4(0.f, 0.f, 0.f, 0.f);
        }
        CP_WAIT1();
        __syncthreads();

        const uint32_t bufb = sb + FF_BB + (ch & 1) * FF_BS;
#pragma unroll
        for (int pass = 0; pass < 3; pass++) {
            const uint32_t aB = sb + ((pass == 1) ? FF_AL : FF_AH) + aLaneOff;
            const uint32_t bB = bufb + ((pass == 2) ? (FF_BS / 2) : 0) + bLaneOff;
#pragma unroll
            for (int ks = 0; ks < 2; ks++) {
                uint32_t aF[4][4];
#pragma unroll
                for (int mt = 0; mt < 4; mt++)
                    LDMX4(aF[mt], aB + (uint32_t)mt * 16 * FFROW + (uint32_t)ks * 32);
                uint32_t bF[2][4];
#pragma unroll
                for (int np = 0; np < 2; np++)
                    LDMX4(bF[np], bB + (uint32_t)np * 16 * FFROW + (uint32_t)ks * 32);
#pragma unroll
                for (int mt = 0; mt < 4; mt++)
#pragma unroll
                    for (int nt = 0; nt < 4; nt++)
                        MMA_BF(acc[mt][nt], aF[mt],
                               bF[nt >> 1][(nt & 1) * 2], bF[nt >> 1][(nt & 1) * 2 + 1]);
            }
        }
        __syncthreads();
    }

    float2 bv[4];
#pragma unroll
    for (int nt = 0; nt < 4; nt++)
        bv[nt] = *(const float2*)&bias[wn * 32 + nt * 8 + (lane & 3) * 2];

#pragma unroll
    for (int mt = 0; mt < 4; mt++) {
#pragma unroll
        for (int half = 0; half < 2; half++) {
            const int row  = wm * 64 + mt * 16 + (lane >> 2) + half * 8;
            const int grow = m0 + row;
            if (grow >= M) continue;
#pragma unroll
            for (int nt = 0; nt < 4; nt++) {
                const int col = wn * 32 + nt * 8 + (lane & 3) * 2;
                float f0 = fmaxf(acc[mt][nt][half * 2 + 0] + bv[nt].x, 0.f);
                float f1 = fmaxf(acc[mt][nt][half * 2 + 1] + bv[nt].y, 0.f);
                if (branch == 0) {
                    __half h0, l0, h1, l1;
                    split_fp16(f0, h0, l0); split_fp16(f1, h1, l1);
                    *(uint32_t*)&g_headH[(size_t)grow * HSZ + col] = pack_fp16(h0, h1);
                    *(uint32_t*)&g_headL[(size_t)grow * HSZ + col] = pack_fp16(l0, l1);
                } else {
                    *(float2*)&g_tail[(size_t)grow * HSZ + col] = make_float2(f0, f1);
                }
            }
        }
    }
}

// ---------------------------------------------------------------------------
// Kernel 2: biaffine v4 — fp16 2-pass. CTA = 128 tokens x 24 r, 256 threads,
// warp tile m16 x n128. A (head fp16 hi/lo) in smem; B fp16-hi streamed as
// LDG.128 fragments; warp-local epilogue. No mainloop barriers.
//   D = (Ah + Al) * Bh   (dropped A*Bl term ~ 2^-11 relative)
// ---------------------------------------------------------------------------
#define AROW 272
#define ATILE (128 * AROW)
#define BI_SMEM (2 * ATILE)            // 69632

__global__ __launch_bounds__(256, 2) void biaffine_mma(
    const int* __restrict__ head_id,
    float* __restrict__ out)
{
    extern __shared__ char sm[];
    const uint32_t sb = smem_u32(sm);

    const int t0  = blockIdx.x * 128;
    const int r0  = blockIdx.y * 24;
    const int tid = threadIdx.x;
    const int lane = tid & 31;
    const int warp = tid >> 5;

#pragma unroll
    for (int i = 0; i < 8; i++) {
        int c   = tid + i * 256;
        int row = c >> 4;
        int col = c & 15;
        int t   = t0 + row;
        int hid = head_id[t];
        size_t base = ((size_t)(t >> 10) * APP + hid) * HSZ + col * 8;
        uint32_t so = (uint32_t)row * AROW + col * 16;
        CP16(sb + so, g_headH + base);
        CP16(sb + ATILE + so, g_headL + base);
    }
    CP_COMMIT();
    CP_WAIT0();
    __syncthreads();

    const uint32_t aAddrH = sb + (uint32_t)(warp * 16 + (lane & 15)) * AROW
                          + (uint32_t)(lane >> 4) * 16;
    const uint32_t aAddrL = aAddrH + ATILE;

    const int trow_lo = t0 + warp * 16 + (lane >> 2);
    const int trow_hi = trow_lo + 8;
    const float* tl = g_tail + (size_t)trow_lo * HSZ + (lane & 3) * 2;
    const float* th = g_tail + (size_t)trow_hi * HSZ + (lane & 3) * 2;

#pragma unroll 1
    for (int rr = 0; rr < 24; rr++) {
        const int r = r0 + rr;
        const uint4* __restrict__ bF = g_Bfrag + (size_t)r * 2048 + lane;

        float acc[16][4];
#pragma unroll
        for (int nb = 0; nb < 16; nb++)
#pragma unroll
            for (int e = 0; e < 4; e++) acc[nb][e] = 0.f;

#pragma unroll
        for (int ks = 0; ks < 8; ks++) {
            uint32_t aH[4], aL[4];
            LDMX4(aH, aAddrH + ks * 32);
            LDMX4(aL, aAddrL + ks * 32);
            const uint4* bk = bF + ks * 256;
#pragma unroll
            for (int g = 0; g < 8; g++) {
                uint4 bv = bk[g * 32];
                MMA_FP(acc[2 * g],     aH, bv.x, bv.y);
                MMA_FP(acc[2 * g + 1], aH, bv.z, bv.w);
                MMA_FP(acc[2 * g],     aL, bv.x, bv.y);
                MMA_FP(acc[2 * g + 1], aL, bv.z, bv.w);
            }
        }

        float plo = 0.f, phi = 0.f;
#pragma unroll
        for (int nb = 0; nb < 16; nb++) {
            float2 a = *(const float2*)(tl + nb * 8);
            float2 b = *(const float2*)(th + nb * 8);
            plo += acc[nb][0] * a.x + acc[nb][1] * a.y;
            phi += acc[nb][2] * b.x + acc[nb][3] * b.y;
        }
        plo += __shfl_xor_sync(0xffffffffu, plo, 1);
        plo += __shfl_xor_sync(0xffffffffu, plo, 2);
        phi += __shfl_xor_sync(0xffffffffu, phi, 1);
        phi += __shfl_xor_sync(0xffffffffu, phi, 2);
        if ((lane & 3) == 0) {
            out[(size_t)trow_lo * RSZ + r] = plo;
            out[(size_t)trow_hi * RSZ + r] = phi;
        }
    }
}

// ---------------------------------------------------------------------------
extern "C" void kernel_launch(void* const* d_in, const int* in_sizes, int n_in,
                              void* d_out, int out_size)
{
    const float* x       = (const float*)d_in[0];
    const int*   head_id = (const int*)  d_in[1];
    const float* root    = (const float*)d_in[2];
    const float* Wh      = (const float*)d_in[3];
    const float* bh      = (const float*)d_in[4];
    const float* Wt      = (const float*)d_in[5];
    const float* bt      = (const float*)d_in[6];
    const float* Kmat    = (const float*)d_in[7];
    float*       out     = (float*)d_out;

    const int prep_smem = 128 * 129 * sizeof(float);   // 66048
    cudaFuncSetAttribute(prep_k, cudaFuncAttributeMaxDynamicSharedMemorySize, prep_smem);
    prep_k<<<RSZ, 256, prep_smem>>>(Kmat);
    prep_w<<<dim3(24, 2), 256>>>(Wh, Wt);

    cudaFuncSetAttribute(ff_mma, cudaFuncAttributeMaxDynamicSharedMemorySize, FF_SMEM);
    ff_mma<<<dim3(257, 2), 256, FF_SMEM>>>(x, root, bh, bt);

    cudaFuncSetAttribute(biaffine_mma, cudaFuncAttributeMaxDynamicSharedMemorySize, BI_SMEM);
    biaffine_mma<<<dim3(NTOK / 128, 2), 256, BI_SMEM>>>(head_id, out);
}

// round 8
// speedup vs baseline: 2.5544x; 1.3689x over previous
#include <cuda_runtime.h>
#include <cuda_bf16.h>
#include <cuda_fp16.h>
#include <cstdint>

// Problem constants
#define BSZ   32
#define SSZ   1024
#define DSZ   768
#define HSZ   128
#define RSZ   48
#define APP   (SSZ + 1)        // 1025
#define NTOK  (BSZ * SSZ)      // 32768
#define MHEAD (BSZ * APP)      // 32800

// Scratch (device globals)
__device__ __half g_headH[(size_t)MHEAD * HSZ];           // fp16 head (hi only)
__device__ float  g_tail [(size_t)NTOK * HSZ];
__device__ __half g_W16[(size_t)2 * HSZ * DSZ];           // W^T [branch][n][k] fp16
// Fragment-ordered fp16 B image per r: uint4 units: r*2048 + ks*256 + g*32 + lane
__device__ uint4 g_Bfrag[(size_t)RSZ * 2048];

// ---------------------------------------------------------------------------
// PTX helpers (target-suffix-free)
// ---------------------------------------------------------------------------
__device__ __forceinline__ uint32_t smem_u32(const void* p) {
    uint32_t a;
    asm("{ .reg .u64 t; cvta.to.shared.u64 t, %1; cvt.u32.u64 %0, t; }" : "=r"(a) : "l"(p));
    return a;
}

#define CP16(dst, src) \
    asm volatile("cp.async.cg.shared.global [%0], [%1], 16;" :: "r"(dst), "l"(src) : "memory")
#define CP_COMMIT() asm volatile("cp.async.commit_group;" ::: "memory")
#define CP_WAIT0()  asm volatile("cp.async.wait_group 0;" ::: "memory")
#define CP_WAIT1()  asm volatile("cp.async.wait_group 1;" ::: "memory")

#define LDMX4(r, addr) \
    asm volatile("ldmatrix.sync.aligned.m8n8.x4.shared.b16 {%0,%1,%2,%3}, [%4];" \
        : "=r"((r)[0]), "=r"((r)[1]), "=r"((r)[2]), "=r"((r)[3]) : "r"(addr))

// fp16 MMA
#define MMA_FP(c, a, b0, b1) \
    asm volatile("mma.sync.aligned.m16n8k16.row.col.f32.f16.f16.f32 " \
        "{%0,%1,%2,%3}, {%4,%5,%6,%7}, {%8,%9}, {%0,%1,%2,%3};" \
        : "+f"((c)[0]), "+f"((c)[1]), "+f"((c)[2]), "+f"((c)[3]) \
        : "r"((a)[0]), "r"((a)[1]), "r"((a)[2]), "r"((a)[3]), "r"(b0), "r"(b1))

__device__ __forceinline__ void split_fp16(float v, __half& hi, __half& lo) {
    hi = __float2half_rn(v);
    lo = __float2half_rn(v - __half2float(hi));
}
__device__ __forceinline__ uint32_t pack_fp16(__half a, __half b) {
    return (uint32_t)__half_as_ushort(a) | ((uint32_t)__half_as_ushort(b) << 16);
}

// ---------------------------------------------------------------------------
// Kernel 0a: prep K -> fragment-ordered fp16 B images (hi only).
//   uint32 index v in [0, 8192): v = ks*1024 + g*128 + lane*4 + hw2
//     pair = hw2>>1, reg = hw2&1
//     n = (2g+pair)*8 + (lane>>2); h0 = ks*16 + reg*8 + (lane&3)*2
// ---------------------------------------------------------------------------
__global__ __launch_bounds__(256) void prep_k(const float* __restrict__ Kmat)
{
    extern __shared__ float ksm[];           // [128][129]
    const int r   = blockIdx.x;
    const int tid = threadIdx.x;
#pragma unroll
    for (int j = 0; j < 64; j++) {
        int idx = tid + j * 256;
        int h = idx >> 7, n = idx & 127;
        ksm[h * 129 + n] = Kmat[(size_t)h * (HSZ * RSZ) + r * HSZ + n];
    }
    __syncthreads();

    uint32_t* outH = (uint32_t*)(g_Bfrag + (size_t)r * 2048);
#pragma unroll
    for (int j = 0; j < 32; j++) {
        int v = tid + j * 256;               // 0..8191
        int ks   = v >> 10;
        int rem  = v & 1023;
        int g    = rem >> 7;
        int rem2 = rem & 127;
        int lane = rem2 >> 2;
        int hw2  = rem2 & 3;
        int pair = hw2 >> 1, reg = hw2 & 1;
        int n  = (2 * g + pair) * 8 + (lane >> 2);
        int h0 = ks * 16 + reg * 8 + (lane & 3) * 2;
        float f0 = ksm[h0 * 129 + n];
        float f1 = ksm[(h0 + 1) * 129 + n];
        outH[v] = pack_fp16(__float2half_rn(f0), __float2half_rn(f1));
    }
}

// ---------------------------------------------------------------------------
// Kernel 0b: prep W — transpose Wh/Wt -> fp16 W^T [n][k].
// ---------------------------------------------------------------------------
__global__ __launch_bounds__(256) void prep_w(const float* __restrict__ Wh,
                                              const float* __restrict__ Wt)
{
    __shared__ float tw[32 * 129];
    const int kb = blockIdx.x;
    const int br = blockIdx.y;
    const float* W = br ? Wt : Wh;
    const int tid = threadIdx.x;
#pragma unroll
    for (int j = 0; j < 16; j++) {
        int idx = tid + j * 256;
        int k = idx >> 7;
        int n = idx & 127;
        tw[k * 129 + n] = W[(size_t)(kb * 32 + k) * HSZ + n];
    }
    __syncthreads();
#pragma unroll
    for (int j = 0; j < 16; j++) {
        int idx = tid + j * 256;
        int n = idx >> 5;
        int k = idx & 31;
        g_W16[(size_t)br * HSZ * DSZ + (size_t)n * DSZ + kb * 32 + k] =
            __float2half_rn(tw[k * 129 + n]);
    }
}

// ---------------------------------------------------------------------------
// Kernel 1: dual FF GEMM, fp16 2-pass: (xh + xl) @ Wh16.
//   CTA = 128 rows x 128 cols, K=768 in 24 chunks of 32, 2-stage B pipeline.
// ---------------------------------------------------------------------------
#define FFROW 80
#define FF_AT (128 * FFROW)                        // 10240
#define FF_AH 0
#define FF_AL FF_AT
#define FF_BB (2 * FF_AT)                          // 20480
#define FF_BS FF_AT                                // 10240 per stage (hi only)
#define FF_SMEM (FF_BB + 2 * FF_BS)                // 40960

__global__ __launch_bounds__(256) void ff_mma(
    const float* __restrict__ x,
    const float* __restrict__ root,
    const float* __restrict__ bh, const float* __restrict__ bt)
{
    extern __shared__ char sm[];
    const uint32_t sb = smem_u32(sm);

    const int branch = blockIdx.y;
    const int M      = (branch == 0) ? MHEAD : NTOK;
    const int m0     = blockIdx.x * 128;
    if (m0 >= M) return;

    const float* bias = (branch == 0) ? bh : bt;
    const __half* WB  = g_W16 + (size_t)branch * HSZ * DSZ;

    const int tid  = threadIdx.x;
    const int lane = tid & 31;
    const int warp = tid >> 5;
    const int wm   = warp >> 2;
    const int wn   = warp & 3;

    const float* arow[4];
    bool rowok[4];
    int rown[4], colf[4];
#pragma unroll
    for (int i = 0; i < 4; i++) {
        int c   = tid + i * 256;
        int row = c >> 3;
        int c4  = c & 7;
        rown[i] = row; colf[i] = c4;
        int g = m0 + row;
        const float* p = nullptr;
        bool ok = (g < M);
        if (ok) {
            if (branch == 0) {
                int b  = g / APP;
                int ii = g - b * APP;
                p = (ii == 0) ? root : (x + (size_t)(b * SSZ + (ii - 1)) * DSZ);
            } else {
                p = x + (size_t)g * DSZ;
            }
        }
        arow[i] = p; rowok[i] = ok;
    }

    auto load_B = [&](uint32_t buf, int k0) {
#pragma unroll
        for (int i = 0; i < 2; i++) {
            int c   = tid + i * 256;      // 0..511
            int row = c >> 2;
            int c4  = c & 3;
            CP16(buf + row * FFROW + c4 * 16, WB + (size_t)row * DSZ + k0 + c4 * 8);
        }
    };

    float4 va[4];
#pragma unroll
    for (int i = 0; i < 4; i++)
        va[i] = rowok[i] ? *(const float4*)(arow[i] + colf[i] * 4)
                         : make_float4(0.f, 0.f, 0.f, 0.f);
    load_B(sb + FF_BB, 0);
    CP_COMMIT();

    float acc[4][4][4];
#pragma unroll
    for (int mt = 0; mt < 4; mt++)
#pragma unroll
        for (int nt = 0; nt < 4; nt++)
#pragma unroll
            for (int e = 0; e < 4; e++) acc[mt][nt][e] = 0.f;

    const uint32_t aLaneOff = (uint32_t)(wm * 64 + (lane & 15)) * FFROW
                            + (uint32_t)(lane >> 4) * 16;
    const uint32_t bLaneOff = (uint32_t)(wn * 32 + (lane & 7) + ((lane >> 4) << 3)) * FFROW
                            + (uint32_t)((lane >> 3) & 1) * 16;

#pragma unroll 1
    for (int ch = 0; ch < 24; ch++) {
        const int nxt = ch + 1;
        if (nxt < 24) load_B(sb + FF_BB + (nxt & 1) * FF_BS, nxt * 32);
        CP_COMMIT();

#pragma unroll
        for (int i = 0; i < 4; i++) {
            __half h0, h1, h2, h3, l0, l1, l2, l3;
            split_fp16(va[i].x, h0, l0); split_fp16(va[i].y, h1, l1);
            split_fp16(va[i].z, h2, l2); split_fp16(va[i].w, h3, l3);
            uint32_t off = rown[i] * FFROW + colf[i] * 8;
            *(uint2*)(sm + FF_AH + off) = make_uint2(pack_fp16(h0, h1), pack_fp16(h2, h3));
            *(uint2*)(sm + FF_AL + off) = make_uint2(pack_fp16(l0, l1), pack_fp16(l2, l3));
        }
        if (nxt < 24) {
#pragma unroll
            for (int i = 0; i < 4; i++)
                va[i] = rowok[i] ? *(const float4*)(arow[i] + nxt * 32 + colf[i] * 4)
                                 : make_float4(0.f, 0.f, 0.f, 0.f);
        }
        CP_WAIT1();
        __syncthreads();

        const uint32_t bufb = sb + FF_BB + (ch & 1) * FF_BS;
#pragma unroll
        for (int pass = 0; pass < 2; pass++) {
            const uint32_t aB = sb + ((pass == 1) ? FF_AL : FF_AH) + aLaneOff;
            const uint32_t bB = bufb + bLaneOff;
#pragma unroll
            for (int ks = 0; ks < 2; ks++) {
                uint32_t aF[4][4];
#pragma unroll
                for (int mt = 0; mt < 4; mt++)
                    LDMX4(aF[mt], aB + (uint32_t)mt * 16 * FFROW + (uint32_t)ks * 32);
                uint32_t bF[2][4];
#pragma unroll
                for (int np = 0; np < 2; np++)
                    LDMX4(bF[np], bB + (uint32_t)np * 16 * FFROW + (uint32_t)ks * 32);
#pragma unroll
                for (int mt = 0; mt < 4; mt++)
#pragma unroll
                    for (int nt = 0; nt < 4; nt++)
                        MMA_FP(acc[mt][nt], aF[mt],
                               bF[nt >> 1][(nt & 1) * 2], bF[nt >> 1][(nt & 1) * 2 + 1]);
            }
        }
        __syncthreads();
    }

    float2 bv[4];
#pragma unroll
    for (int nt = 0; nt < 4; nt++)
        bv[nt] = *(const float2*)&bias[wn * 32 + nt * 8 + (lane & 3) * 2];

#pragma unroll
    for (int mt = 0; mt < 4; mt++) {
#pragma unroll
        for (int half = 0; half < 2; half++) {
            const int row  = wm * 64 + mt * 16 + (lane >> 2) + half * 8;
            const int grow = m0 + row;
            if (grow >= M) continue;
#pragma unroll
            for (int nt = 0; nt < 4; nt++) {
                const int col = wn * 32 + nt * 8 + (lane & 3) * 2;
                float f0 = fmaxf(acc[mt][nt][half * 2 + 0] + bv[nt].x, 0.f);
                float f1 = fmaxf(acc[mt][nt][half * 2 + 1] + bv[nt].y, 0.f);
                if (branch == 0) {
                    *(uint32_t*)&g_headH[(size_t)grow * HSZ + col] =
                        pack_fp16(__float2half_rn(f0), __float2half_rn(f1));
                } else {
                    *(float2*)&g_tail[(size_t)grow * HSZ + col] = make_float2(f0, f1);
                }
            }
        }
    }
}

// ---------------------------------------------------------------------------
// Kernel 2: biaffine v5 — fp16 1-pass. CTA = 128 tokens x 24 r, 256 threads,
// warp tile m16 x n128. A (head fp16) in smem; B fp16 streamed as LDG.128
// fragments; warp-local epilogue. No mainloop barriers.
//   D = Ah * Bh
// ---------------------------------------------------------------------------
#define AROW 272
#define ATILE (128 * AROW)
#define BI_SMEM ATILE                  // 34816

__global__ __launch_bounds__(256, 2) void biaffine_mma(
    const int* __restrict__ head_id,
    float* __restrict__ out)
{
    extern __shared__ char sm[];
    const uint32_t sb = smem_u32(sm);

    const int t0  = blockIdx.x * 128;
    const int r0  = blockIdx.y * 24;
    const int tid = threadIdx.x;
    const int lane = tid & 31;
    const int warp = tid >> 5;

#pragma unroll
    for (int i = 0; i < 8; i++) {
        int c   = tid + i * 256;
        int row = c >> 4;
        int col = c & 15;
        int t   = t0 + row;
        int hid = head_id[t];
        size_t base = ((size_t)(t >> 10) * APP + hid) * HSZ + col * 8;
        CP16(sb + (uint32_t)row * AROW + col * 16, g_headH + base);
    }
    CP_COMMIT();
    CP_WAIT0();
    __syncthreads();

    const uint32_t aAddrH = sb + (uint32_t)(warp * 16 + (lane & 15)) * AROW
                          + (uint32_t)(lane >> 4) * 16;

    const int trow_lo = t0 + warp * 16 + (lane >> 2);
    const int trow_hi = trow_lo + 8;
    const float* tl = g_tail + (size_t)trow_lo * HSZ + (lane & 3) * 2;
    const float* th = g_tail + (size_t)trow_hi * HSZ + (lane & 3) * 2;

#pragma unroll 1
    for (int rr = 0; rr < 24; rr++) {
        const int r = r0 + rr;
        const uint4* __restrict__ bF = g_Bfrag + (size_t)r * 2048 + lane;

        float acc[16][4];
#pragma unroll
        for (int nb = 0; nb < 16; nb++)
#pragma unroll
            for (int e = 0; e < 4; e++) acc[nb][e] = 0.f;

#pragma unroll
        for (int ks = 0; ks < 8; ks++) {
            uint32_t aH[4];
            LDMX4(aH, aAddrH + ks * 32);
            const uint4* bk = bF + ks * 256;
#pragma unroll
            for (int g = 0; g < 8; g++) {
                uint4 bv = bk[g * 32];
                MMA_FP(acc[2 * g],     aH, bv.x, bv.y);
                MMA_FP(acc[2 * g + 1], aH, bv.z, bv.w);
            }
        }

        float plo = 0.f, phi = 0.f;
#pragma unroll
        for (int nb = 0; nb < 16; nb++) {
            float2 a = *(const float2*)(tl + nb * 8);
            float2 b = *(const float2*)(th + nb * 8);
            plo += acc[nb][0] * a.x + acc[nb][1] * a.y;
            phi += acc[nb][2] * b.x + acc[nb][3] * b.y;
        }
        plo += __shfl_xor_sync(0xffffffffu, plo, 1);
        plo += __shfl_xor_sync(0xffffffffu, plo, 2);
        phi += __shfl_xor_sync(0xffffffffu, phi, 1);
        phi += __shfl_xor_sync(0xffffffffu, phi, 2);
        if ((lane & 3) == 0) {
            out[(size_t)trow_lo * RSZ + r] = plo;
            out[(size_t)trow_hi * RSZ + r] = phi;
        }
    }
}

// ---------------------------------------------------------------------------
extern "C" void kernel_launch(void* const* d_in, const int* in_sizes, int n_in,
                              void* d_out, int out_size)
{
    const float* x       = (const float*)d_in[0];
    const int*   head_id = (const int*)  d_in[1];
    const float* root    = (const float*)d_in[2];
    const float* Wh      = (const float*)d_in[3];
    const float* bh      = (const float*)d_in[4];
    const float* Wt      = (const float*)d_in[5];
    const float* bt      = (const float*)d_in[6];
    const float* Kmat    = (const float*)d_in[7];
    float*       out     = (float*)d_out;

    const int prep_smem = 128 * 129 * sizeof(float);   // 66048
    cudaFuncSetAttribute(prep_k, cudaFuncAttributeMaxDynamicSharedMemorySize, prep_smem);
    prep_k<<<RSZ, 256, prep_smem>>>(Kmat);
    prep_w<<<dim3(24, 2), 256>>>(Wh, Wt);

    cudaFuncSetAttribute(ff_mma, cudaFuncAttributeMaxDynamicSharedMemorySize, FF_SMEM);
    ff_mma<<<dim3(257, 2), 256, FF_SMEM>>>(x, root, bh, bt);

    cudaFuncSetAttribute(biaffine_mma, cudaFuncAttributeMaxDynamicSharedMemorySize, BI_SMEM);
    biaffine_mma<<<dim3(NTOK / 128, 2), 256, BI_SMEM>>>(head_id, out);
}

// round 9
// speedup vs baseline: 3.4242x; 1.3405x over previous
#include <cuda_runtime.h>
#include <cuda_bf16.h>
#include <cuda_fp16.h>
#include <cstdint>

// Problem constants
#define BSZ   32
#define SSZ   1024
#define DSZ   768
#define HSZ   128
#define RSZ   48
#define APP   (SSZ + 1)        // 1025
#define NTOK  (BSZ * SSZ)      // 32768
#define MHEAD (BSZ * APP)      // 32800

// Scratch (device globals)
__device__ __half g_headH[(size_t)MHEAD * HSZ];           // fp16 head
__device__ __half g_tailH[(size_t)NTOK * HSZ];            // fp16 tail
__device__ __half g_W16[(size_t)2 * HSZ * DSZ];           // W^T [branch][n][k] fp16
// Fragment-ordered fp16 B image per r: uint4 units: r*2048 + ks*256 + g*32 + lane
__device__ uint4 g_Bfrag[(size_t)RSZ * 2048];

// ---------------------------------------------------------------------------
// PTX helpers (target-suffix-free)
// ---------------------------------------------------------------------------
__device__ __forceinline__ uint32_t smem_u32(const void* p) {
    uint32_t a;
    asm("{ .reg .u64 t; cvta.to.shared.u64 t, %1; cvt.u32.u64 %0, t; }" : "=r"(a) : "l"(p));
    return a;
}

#define CP16(dst, src) \
    asm volatile("cp.async.cg.shared.global [%0], [%1], 16;" :: "r"(dst), "l"(src) : "memory")
#define CP_COMMIT() asm volatile("cp.async.commit_group;" ::: "memory")
#define CP_WAIT0()  asm volatile("cp.async.wait_group 0;" ::: "memory")
#define CP_WAIT1()  asm volatile("cp.async.wait_group 1;" ::: "memory")

#define LDMX4(r, addr) \
    asm volatile("ldmatrix.sync.aligned.m8n8.x4.shared.b16 {%0,%1,%2,%3}, [%4];" \
        : "=r"((r)[0]), "=r"((r)[1]), "=r"((r)[2]), "=r"((r)[3]) : "r"(addr))

// fp16 MMA
#define MMA_FP(c, a, b0, b1) \
    asm volatile("mma.sync.aligned.m16n8k16.row.col.f32.f16.f16.f32 " \
        "{%0,%1,%2,%3}, {%4,%5,%6,%7}, {%8,%9}, {%0,%1,%2,%3};" \
        : "+f"((c)[0]), "+f"((c)[1]), "+f"((c)[2]), "+f"((c)[3]) \
        : "r"((a)[0]), "r"((a)[1]), "r"((a)[2]), "r"((a)[3]), "r"(b0), "r"(b1))

__device__ __forceinline__ void split_fp16(float v, __half& hi, __half& lo) {
    hi = __float2half_rn(v);
    lo = __float2half_rn(v - __half2float(hi));
}
__device__ __forceinline__ uint32_t pack_fp16(__half a, __half b) {
    return (uint32_t)__half_as_ushort(a) | ((uint32_t)__half_as_ushort(b) << 16);
}

// ---------------------------------------------------------------------------
// Kernel 0a: prep K -> fragment-ordered fp16 B images.
//   uint32 index v in [0, 8192): v = ks*1024 + g*128 + lane*4 + hw2
//     pair = hw2>>1, reg = hw2&1
//     n = (2g+pair)*8 + (lane>>2); h0 = ks*16 + reg*8 + (lane&3)*2
// ---------------------------------------------------------------------------
__global__ __launch_bounds__(256) void prep_k(const float* __restrict__ Kmat)
{
    extern __shared__ float ksm[];           // [128][129]
    const int r   = blockIdx.x;
    const int tid = threadIdx.x;
#pragma unroll
    for (int j = 0; j < 64; j++) {
        int idx = tid + j * 256;
        int h = idx >> 7, n = idx & 127;
        ksm[h * 129 + n] = Kmat[(size_t)h * (HSZ * RSZ) + r * HSZ + n];
    }
    __syncthreads();

    uint32_t* outH = (uint32_t*)(g_Bfrag + (size_t)r * 2048);
#pragma unroll
    for (int j = 0; j < 32; j++) {
        int v = tid + j * 256;               // 0..8191
        int ks   = v >> 10;
        int rem  = v & 1023;
        int g    = rem >> 7;
        int rem2 = rem & 127;
        int lane = rem2 >> 2;
        int hw2  = rem2 & 3;
        int pair = hw2 >> 1, reg = hw2 & 1;
        int n  = (2 * g + pair) * 8 + (lane >> 2);
        int h0 = ks * 16 + reg * 8 + (lane & 3) * 2;
        float f0 = ksm[h0 * 129 + n];
        float f1 = ksm[(h0 + 1) * 129 + n];
        outH[v] = pack_fp16(__float2half_rn(f0), __float2half_rn(f1));
    }
}

// ---------------------------------------------------------------------------
// Kernel 0b: prep W — transpose Wh/Wt -> fp16 W^T [n][k].
// ---------------------------------------------------------------------------
__global__ __launch_bounds__(256) void prep_w(const float* __restrict__ Wh,
                                              const float* __restrict__ Wt)
{
    __shared__ float tw[32 * 129];
    const int kb = blockIdx.x;
    const int br = blockIdx.y;
    const float* W = br ? Wt : Wh;
    const int tid = threadIdx.x;
#pragma unroll
    for (int j = 0; j < 16; j++) {
        int idx = tid + j * 256;
        int k = idx >> 7;
        int n = idx & 127;
        tw[k * 129 + n] = W[(size_t)(kb * 32 + k) * HSZ + n];
    }
    __syncthreads();
#pragma unroll
    for (int j = 0; j < 16; j++) {
        int idx = tid + j * 256;
        int n = idx >> 5;
        int k = idx & 31;
        g_W16[(size_t)br * HSZ * DSZ + (size_t)n * DSZ + kb * 32 + k] =
            __float2half_rn(tw[k * 129 + n]);
    }
}

// ---------------------------------------------------------------------------
// Kernel 1: dual FF GEMM, fp16 2-pass: (xh + xl) @ W16.
//   CTA = 128 rows x 128 cols, K=768 in 24 chunks of 32, 2-stage B pipeline.
//   Branch 0 emits fp16 head; branch 1 emits fp16 tail.
// ---------------------------------------------------------------------------
#define FFROW 80
#define FF_AT (128 * FFROW)                        // 10240
#define FF_AH 0
#define FF_AL FF_AT
#define FF_BB (2 * FF_AT)                          // 20480
#define FF_BS FF_AT                                // 10240 per stage
#define FF_SMEM (FF_BB + 2 * FF_BS)                // 40960

__global__ __launch_bounds__(256) void ff_mma(
    const float* __restrict__ x,
    const float* __restrict__ root,
    const float* __restrict__ bh, const float* __restrict__ bt)
{
    extern __shared__ char sm[];
    const uint32_t sb = smem_u32(sm);

    const int branch = blockIdx.y;
    const int M      = (branch == 0) ? MHEAD : NTOK;
    const int m0     = blockIdx.x * 128;
    if (m0 >= M) return;

    const float* bias = (branch == 0) ? bh : bt;
    const __half* WB  = g_W16 + (size_t)branch * HSZ * DSZ;

    const int tid  = threadIdx.x;
    const int lane = tid & 31;
    const int warp = tid >> 5;
    const int wm   = warp >> 2;
    const int wn   = warp & 3;

    const float* arow[4];
    bool rowok[4];
    int rown[4], colf[4];
#pragma unroll
    for (int i = 0; i < 4; i++) {
        int c   = tid + i * 256;
        int row = c >> 3;
        int c4  = c & 7;
        rown[i] = row; colf[i] = c4;
        int g = m0 + row;
        const float* p = nullptr;
        bool ok = (g < M);
        if (ok) {
            if (branch == 0) {
                int b  = g / APP;
                int ii = g - b * APP;
                p = (ii == 0) ? root : (x + (size_t)(b * SSZ + (ii - 1)) * DSZ);
            } else {
                p = x + (size_t)g * DSZ;
            }
        }
        arow[i] = p; rowok[i] = ok;
    }

    auto load_B = [&](uint32_t buf, int k0) {
#pragma unroll
        for (int i = 0; i < 2; i++) {
            int c   = tid + i * 256;
            int row = c >> 2;
            int c4  = c & 3;
            CP16(buf + row * FFROW + c4 * 16, WB + (size_t)row * DSZ + k0 + c4 * 8);
        }
    };

    float4 va[4];
#pragma unroll
    for (int i = 0; i < 4; i++)
        va[i] = rowok[i] ? *(const float4*)(arow[i] + colf[i] * 4)
                         : make_float4(0.f, 0.f, 0.f, 0.f);
    load_B(sb + FF_BB, 0);
    CP_COMMIT();

    float acc[4][4][4];
#pragma unroll
    for (int mt = 0; mt < 4; mt++)
#pragma unroll
        for (int nt = 0; nt < 4; nt++)
#pragma unroll
            for (int e = 0; e < 4; e++) acc[mt][nt][e] = 0.f;

    const uint32_t aLaneOff = (uint32_t)(wm * 64 + (lane & 15)) * FFROW
                            + (uint32_t)(lane >> 4) * 16;
    const uint32_t bLaneOff = (uint32_t)(wn * 32 + (lane & 7) + ((lane >> 4) << 3)) * FFROW
                            + (uint32_t)((lane >> 3) & 1) * 16;

#pragma unroll 1
    for (int ch = 0; ch < 24; ch++) {
        const int nxt = ch + 1;
        if (nxt < 24) load_B(sb + FF_BB + (nxt & 1) * FF_BS, nxt * 32);
        CP_COMMIT();

#pragma unroll
        for (int i = 0; i < 4; i++) {
            __half h0, h1, h2, h3, l0, l1, l2, l3;
            split_fp16(va[i].x, h0, l0); split_fp16(va[i].y, h1, l1);
            split_fp16(va[i].z, h2, l2); split_fp16(va[i].w, h3, l3);
            uint32_t off = rown[i] * FFROW + colf[i] * 8;
            *(uint2*)(sm + FF_AH + off) = make_uint2(pack_fp16(h0, h1), pack_fp16(h2, h3));
            *(uint2*)(sm + FF_AL + off) = make_uint2(pack_fp16(l0, l1), pack_fp16(l2, l3));
        }
        if (nxt < 24) {
#pragma unroll
            for (int i = 0; i < 4; i++)
                va[i] = rowok[i] ? *(const float4*)(arow[i] + nxt * 32 + colf[i] * 4)
                                 : make_float4(0.f, 0.f, 0.f, 0.f);
        }
        CP_WAIT1();
        __syncthreads();

        const uint32_t bufb = sb + FF_BB + (ch & 1) * FF_BS;
#pragma unroll
        for (int pass = 0; pass < 2; pass++) {
            const uint32_t aB = sb + ((pass == 1) ? FF_AL : FF_AH) + aLaneOff;
            const uint32_t bB = bufb + bLaneOff;
#pragma unroll
            for (int ks = 0; ks < 2; ks++) {
                uint32_t aF[4][4];
#pragma unroll
                for (int mt = 0; mt < 4; mt++)
                    LDMX4(aF[mt], aB + (uint32_t)mt * 16 * FFROW + (uint32_t)ks * 32);
                uint32_t bF[2][4];
#pragma unroll
                for (int np = 0; np < 2; np++)
                    LDMX4(bF[np], bB + (uint32_t)np * 16 * FFROW + (uint32_t)ks * 32);
#pragma unroll
                for (int mt = 0; mt < 4; mt++)
#pragma unroll
                    for (int nt = 0; nt < 4; nt++)
                        MMA_FP(acc[mt][nt], aF[mt],
                               bF[nt >> 1][(nt & 1) * 2], bF[nt >> 1][(nt & 1) * 2 + 1]);
            }
        }
        __syncthreads();
    }

    float2 bv[4];
#pragma unroll
    for (int nt = 0; nt < 4; nt++)
        bv[nt] = *(const float2*)&bias[wn * 32 + nt * 8 + (lane & 3) * 2];

#pragma unroll
    for (int mt = 0; mt < 4; mt++) {
#pragma unroll
        for (int half = 0; half < 2; half++) {
            const int row  = wm * 64 + mt * 16 + (lane >> 2) + half * 8;
            const int grow = m0 + row;
            if (grow >= M) continue;
#pragma unroll
            for (int nt = 0; nt < 4; nt++) {
                const int col = wn * 32 + nt * 8 + (lane & 3) * 2;
                float f0 = fmaxf(acc[mt][nt][half * 2 + 0] + bv[nt].x, 0.f);
                float f1 = fmaxf(acc[mt][nt][half * 2 + 1] + bv[nt].y, 0.f);
                uint32_t pk = pack_fp16(__float2half_rn(f0), __float2half_rn(f1));
                if (branch == 0)
                    *(uint32_t*)&g_headH[(size_t)grow * HSZ + col] = pk;
                else
                    *(uint32_t*)&g_tailH[(size_t)grow * HSZ + col] = pk;
            }
        }
    }
}

// ---------------------------------------------------------------------------
// Kernel 2: biaffine v6 — fp16 1-pass, warp tile m32 x n64.
//   CTA = 128 tokens x 24 r, 256 threads, 8 warps = 4 m-groups x 2 n-groups.
//   A (head fp16) + tail (fp16) resident in smem; each warp reads only its
//   n64 half of the B fragments (halves B traffic vs n128).
//   Epilogue: warp-local quad reduce, then 2-warp combine via smem red
//   (double-buffered, one __syncthreads per r).
// ---------------------------------------------------------------------------
#define AROW 272
#define ATILE (128 * AROW)             // 34816
#define TTILE (128 * AROW)             // tail fp16, same pitch
#define BI_RED (ATILE + TTILE)         // 2 x 128 floats
#define BI_SMEM (BI_RED + 1024)        // 70656

__global__ __launch_bounds__(256, 2) void biaffine_mma(
    const int* __restrict__ head_id,
    float* __restrict__ out)
{
    extern __shared__ char sm[];
    const uint32_t sb = smem_u32(sm);
    float* red = (float*)(sm + BI_RED);

    const int t0  = blockIdx.x * 128;
    const int r0  = blockIdx.y * 24;
    const int tid = threadIdx.x;
    const int lane = tid & 31;
    const int warp = tid >> 5;
    const int wm   = warp >> 1;        // 0..3 (32 tokens each)
    const int wn   = warp & 1;         // 0..1 (64 k-cols each)

    // Stage A (gathered head rows) and tail, both fp16, via cp.async.
#pragma unroll
    for (int i = 0; i < 8; i++) {
        int c   = tid + i * 256;
        int row = c >> 4;
        int col = c & 15;
        int t   = t0 + row;
        int hid = head_id[t];
        size_t hbase = ((size_t)(t >> 10) * APP + hid) * HSZ + col * 8;
        CP16(sb + (uint32_t)row * AROW + col * 16, g_headH + hbase);
        CP16(sb + ATILE + (uint32_t)row * AROW + col * 16,
             g_tailH + (size_t)t * HSZ + col * 8);
    }
    CP_COMMIT();
    CP_WAIT0();
    __syncthreads();

    const uint32_t aBase = sb + (uint32_t)(wm * 32 + (lane & 15)) * AROW
                         + (uint32_t)(lane >> 4) * 16;

    // tail smem read bases per (mt, half): row = wm*32 + mt*16 + (lane>>2) + half*8
    const char* tbase = sm + ATILE
                      + ((uint32_t)(wm * 32 + (lane >> 2)) * AROW)
                      + (uint32_t)(wn * 64 + (lane & 3) * 2) * 2;

#pragma unroll 1
    for (int rr = 0; rr < 24; rr++) {
        const int r = r0 + rr;
        // warp's half of B fragments: g' = wn*4 + gl -> uint4 offset wn*128
        const uint4* __restrict__ bF = g_Bfrag + (size_t)r * 2048 + wn * 128 + lane;

        float acc[2][8][4];
#pragma unroll
        for (int mt = 0; mt < 2; mt++)
#pragma unroll
            for (int nb = 0; nb < 8; nb++)
#pragma unroll
                for (int e = 0; e < 4; e++) acc[mt][nb][e] = 0.f;

#pragma unroll
        for (int ks = 0; ks < 8; ks++) {
            uint32_t a0[4], a1[4];
            LDMX4(a0, aBase + ks * 32);
            LDMX4(a1, aBase + 16 * AROW + ks * 32);
            const uint4* bk = bF + ks * 256;
#pragma unroll
            for (int gl = 0; gl < 4; gl++) {
                uint4 bv = bk[gl * 32];
                MMA_FP(acc[0][2 * gl],     a0, bv.x, bv.y);
                MMA_FP(acc[0][2 * gl + 1], a0, bv.z, bv.w);
                MMA_FP(acc[1][2 * gl],     a1, bv.x, bv.y);
                MMA_FP(acc[1][2 * gl + 1], a1, bv.z, bv.w);
            }
        }

        // partial k-dot with tail (this warp's 64 cols), quad reduce
        float p[2][2];
#pragma unroll
        for (int mt = 0; mt < 2; mt++) {
#pragma unroll
            for (int half = 0; half < 2; half++) {
                const char* trow = tbase + (uint32_t)(mt * 16 + half * 8) * AROW;
                float s = 0.f;
#pragma unroll
                for (int nb = 0; nb < 8; nb++) {
                    uint32_t tv = *(const uint32_t*)(trow + nb * 16);
                    float2 tf = __half22float2(*(const __half2*)&tv);
                    s += acc[mt][nb][half * 2 + 0] * tf.x
                       + acc[mt][nb][half * 2 + 1] * tf.y;
                }
                s += __shfl_xor_sync(0xffffffffu, s, 1);
                s += __shfl_xor_sync(0xffffffffu, s, 2);
                p[mt][half] = s;
            }
        }

        float* rbuf = red + (rr & 1) * 128;
        if (wn == 0 && (lane & 3) == 0) {
#pragma unroll
            for (int mt = 0; mt < 2; mt++)
#pragma unroll
                for (int half = 0; half < 2; half++) {
                    int lrow = wm * 32 + mt * 16 + (lane >> 2) + half * 8;
                    rbuf[lrow] = p[mt][half];
                }
        }
        __syncthreads();
        if (wn == 1 && (lane & 3) == 0) {
#pragma unroll
            for (int mt = 0; mt < 2; mt++)
#pragma unroll
                for (int half = 0; half < 2; half++) {
                    int lrow = wm * 32 + mt * 16 + (lane >> 2) + half * 8;
                    out[(size_t)(t0 + lrow) * RSZ + r] = rbuf[lrow] + p[mt][half];
                }
        }
    }
}

// ---------------------------------------------------------------------------
extern "C" void kernel_launch(void* const* d_in, const int* in_sizes, int n_in,
                              void* d_out, int out_size)
{
    const float* x       = (const float*)d_in[0];
    const int*   head_id = (const int*)  d_in[1];
    const float* root    = (const float*)d_in[2];
    const float* Wh      = (const float*)d_in[3];
    const float* bh      = (const float*)d_in[4];
    const float* Wt      = (const float*)d_in[5];
    const float* bt      = (const float*)d_in[6];
    const float* Kmat    = (const float*)d_in[7];
    float*       out     = (float*)d_out;

    const int prep_smem = 128 * 129 * sizeof(float);   // 66048
    cudaFuncSetAttribute(prep_k, cudaFuncAttributeMaxDynamicSharedMemorySize, prep_smem);
    prep_k<<<RSZ, 256, prep_smem>>>(Kmat);
    prep_w<<<dim3(24, 2), 256>>>(Wh, Wt);

    cudaFuncSetAttribute(ff_mma, cudaFuncAttributeMaxDynamicSharedMemorySize, FF_SMEM);
    ff_mma<<<dim3(257, 2), 256, FF_SMEM>>>(x, root, bh, bt);

    cudaFuncSetAttribute(biaffine_mma, cudaFuncAttributeMaxDynamicSharedMemorySize, BI_SMEM);
    biaffine_mma<<<dim3(NTOK / 128, 2), 256, BI_SMEM>>>(head_id, out);
}